// round 13
// baseline (speedup 1.0000x reference)
#include <cuda_runtime.h>
#include <cuda_fp16.h>
#include <cstdint>

#define Bb   64
#define Tt   256
#define Ii   256
#define Hh   1024
#define Gg   4096
#define Oo   256
#define NGT  64             // gate tiles (M=64)
#define NYT  4              // y tiles (M=64)
#define NBLK (NGT + NYT)    // 68 CTAs
#define NTHR 512
#define CH   128            // k per chunk
#define MR   64             // M rows per tile
#define ACH  8192           // halves per A chunk (64 rows x 128, swizzled)
#define BCH  8192           // halves per B chunk (128 rows x 64, swizzled)
#define AB   (ACH * 2)      // 16384 B
#define BB   (BCH * 2)      // 16384 B
#define STG  6
#define W1CH 10
#define W2CH 18
#define XCH  2
#define HCH  8
#define HPH  (HCH * BCH)    // halves per h parity buffer
#define RSLAB 2112          // 64*33 floats per warp partial slab

// smem layout (byte offsets from 1024-aligned base)
#define A_OFF  0
#define B_OFF  (STG * AB)                 // 98304
#define BAR_OFF (B_OFF + STG * BB)        // 196608
#define SMEM_USED (BAR_OFF + 64)
#define SMEM_TOTAL (SMEM_USED + 1024)

// ---------------- device-global scratch (packed swizzled smem images) --------
__device__ __align__(16) __half g_W1p[(size_t)NGT * W1CH * ACH];
__device__ __align__(16) __half g_W2p[(size_t)NGT * W2CH * ACH];
__device__ __align__(16) __half g_Wlp[(size_t)NYT * W1CH * ACH];
__device__ __align__(16) __half g_xp [(size_t)Tt * XCH * BCH];
__device__ __align__(16) __half g_h1p[2 * HPH];
__device__ __align__(16) __half g_h2p[2 * HPH];
__device__ float g_c1[Hh * Bb];
__device__ float g_c2[Hh * Bb];
__device__ float g_b1[Gg];
__device__ float g_b2[Gg];
__device__ float g_bl[Oo];
__device__ unsigned g_bar;

// swizzled offsets (halves): 16B groups XORed by row&7 -> conflict-free ldmatrix
__device__ __forceinline__ uint32_t aswz(int row, int k) {   // A: 128-half rows
    return (uint32_t)(row * 128 + (((k >> 3) ^ (row & 7)) << 3) + (k & 7));
}
__device__ __forceinline__ uint32_t bswz(int krow, int b) {  // B: 64-half rows
    return (uint32_t)(krow * 64 + (((b >> 3) ^ (krow & 7)) << 3) + (b & 7));
}

// ---------------- merged prep kernel ----------------
__global__ void prep_all(
    const float* __restrict__ x,
    const float* __restrict__ Wih1, const float* __restrict__ Whh1,
    const float* __restrict__ bi1,  const float* __restrict__ bh1,
    const float* __restrict__ Wih2, const float* __restrict__ Whh2,
    const float* __restrict__ bi2,  const float* __restrict__ bh2,
    const float* __restrict__ Wl,   const float* __restrict__ bl)
{
    const size_t idx = (size_t)blockIdx.x * blockDim.x + threadIdx.x;

    // W2p: logical [tile 64][chunk 18][row 64][k 128] -> swizzled image
    if (idx < (size_t)NGT * W2CH * ACH) {
        int tile = (int)(idx / (W2CH * ACH));
        int r1 = (int)(idx - (size_t)tile * (W2CH * ACH));
        int chunk = r1 / ACH, r2 = r1 - chunk * ACH;
        int row = r2 >> 7, k = r2 & 127;
        int gr = tile * MR + row;
        int u = gr >> 2, gt = gr & 3, orow = gt * Hh + u;
        int kk = chunk * CH + k;
        float v = (kk < Ii + Hh) ? Wih2[(size_t)orow * (Ii + Hh) + kk]
                                 : Whh2[(size_t)orow * Hh + (kk - Ii - Hh)];
        g_W2p[((size_t)tile * W2CH + chunk) * ACH + aswz(row, k)] = __float2half(v);
    }
    // W1p
    if (idx < (size_t)NGT * W1CH * ACH) {
        int tile = (int)(idx / (W1CH * ACH));
        int r1 = (int)(idx - (size_t)tile * (W1CH * ACH));
        int chunk = r1 / ACH, r2 = r1 - chunk * ACH;
        int row = r2 >> 7, k = r2 & 127;
        int gr = tile * MR + row;
        int u = gr >> 2, gt = gr & 3, orow = gt * Hh + u;
        int kk = chunk * CH + k;
        float v = (kk < Ii) ? Wih1[(size_t)orow * Ii + kk]
                            : Whh1[(size_t)orow * Hh + (kk - Ii)];
        g_W1p[((size_t)tile * W1CH + chunk) * ACH + aswz(row, k)] = __float2half(v);
    }
    // Wlp (no gate permute)
    if (idx < (size_t)NYT * W1CH * ACH) {
        int tile = (int)(idx / (W1CH * ACH));
        int r1 = (int)(idx - (size_t)tile * (W1CH * ACH));
        int chunk = r1 / ACH, r2 = r1 - chunk * ACH;
        int row = r2 >> 7, k = r2 & 127;
        int m = tile * MR + row;
        int kk = chunk * CH + k;
        float v = Wl[(size_t)m * (Ii + Hh) + kk];
        g_Wlp[((size_t)tile * W1CH + chunk) * ACH + aswz(row, k)] = __float2half(v);
    }
    // xp: logical [t][chunk 2][krow 128][b 64]
    if (idx < (size_t)Tt * XCH * BCH) {
        int t = (int)(idx / (XCH * BCH));
        int r1 = (int)(idx - (size_t)t * (XCH * BCH));
        int chunk = r1 / BCH, r2 = r1 - chunk * BCH;
        int krow = r2 >> 6, b = r2 & 63;
        float v = x[((size_t)b * Tt + t) * Ii + chunk * CH + krow];
        g_xp[((size_t)t * XCH + chunk) * BCH + bswz(krow, b)] = __float2half(v);
    }
    if (idx < 2 * HPH) { g_h1p[idx] = __float2half(0.f); g_h2p[idx] = __float2half(0.f); }
    if (idx < Hh * Bb) { g_c1[idx] = 0.f; g_c2[idx] = 0.f; }
    if (idx < Gg) {
        int u = (int)idx >> 2, gt = (int)idx & 3;
        g_b1[idx] = bi1[gt * Hh + u] + bh1[gt * Hh + u];
        g_b2[idx] = bi2[gt * Hh + u] + bh2[gt * Hh + u];
    }
    if (idx < Oo) g_bl[idx] = bl[idx];
    if (idx == 0) g_bar = 0u;
}

// ---------------- helpers ----------------
struct Seg { const __half* z; int chunks; };

__device__ __forceinline__ float sigf(float x) { return 1.f / (1.f + __expf(-x)); }

__device__ __forceinline__ void gbar(unsigned target) {
    __syncthreads();
    if (threadIdx.x == 0) {
        asm volatile("red.release.gpu.global.add.u32 [%0], %1;\n"
                     :: "l"(&g_bar), "r"(1u) : "memory");
        unsigned v;
        do {
            asm volatile("ld.acquire.gpu.global.u32 %0, [%1];\n"
                         : "=r"(v) : "l"(&g_bar) : "memory");
        } while (v < target);
    }
    __syncthreads();
}

__device__ __forceinline__ void mbar_wait(uint32_t bar, unsigned parity) {
    asm volatile(
        "{\n\t.reg .pred P;\n"
        "WAIT_%=:\n\t"
        "mbarrier.try_wait.parity.shared.b64 P, [%0], %1;\n\t"
        "@P bra.uni DONE_%=;\n\t"
        "bra.uni WAIT_%=;\n"
        "DONE_%=:\n\t}"
        :: "r"(bar), "r"(parity) : "memory");
}

__device__ __forceinline__ void bulk_to(uint32_t dst, const void* src, unsigned bytes,
                                        uint32_t bar) {
    asm volatile("cp.async.bulk.shared::cta.global.mbarrier::complete_tx::bytes "
                 "[%0], [%1], %2, [%3];\n"
                 :: "r"(dst), "l"(src), "r"(bytes), "r"(bar) : "memory");
}

// issue one chunk's A (weight) + B (z) bulk copies; tid 0 only
__device__ __forceinline__ void issue_chunk(
    const __half* __restrict__ WpA, int j, const Seg segs[3],
    uint32_t sA, uint32_t sB, uint32_t bar)
{
    asm volatile("mbarrier.arrive.expect_tx.shared.b64 _, [%0], %1;\n"
                 :: "r"(bar), "r"((unsigned)(AB + BB)) : "memory");
    bulk_to(sA, WpA + (size_t)j * ACH, AB, bar);
    int jj = j, s = 0;
    if (jj >= segs[0].chunks) { jj -= segs[0].chunks; s = 1; }
    if (s == 1 && jj >= segs[1].chunks) { jj -= segs[1].chunks; s = 2; }
    bulk_to(sB, segs[s].z + (size_t)jj * BCH, BB, bar);
}

// compute one 128-k chunk; warp owns 64m x 32n x 16k (g = k-group, nh = n-half)
__device__ __forceinline__ void compute_chunk(
    uint32_t sA, uint32_t sB, float (&acc)[16][4], int lane, int g, int nh)
{
    const int r16 = lane & 15, cs = lane >> 4;
    unsigned a[4][4], b[2][4];
#pragma unroll
    for (int mi = 0; mi < 4; ++mi) {
        const int row = mi * 16 + r16;
        const int ga = g * 2 + cs;                   // 16B group (k16 block)
        uint32_t aaddr = sA + (uint32_t)(row * 256 + ((ga ^ (row & 7)) << 4));
        asm volatile("ldmatrix.sync.aligned.m8n8.x4.shared.b16 {%0,%1,%2,%3}, [%4];\n"
                     : "=r"(a[mi][0]), "=r"(a[mi][1]), "=r"(a[mi][2]), "=r"(a[mi][3])
                     : "r"(aaddr));
    }
#pragma unroll
    for (int nq = 0; nq < 2; ++nq) {
        const int krow = g * 16 + r16;
        const int gb = nh * 4 + nq * 2 + cs;         // 16B group (batch)
        uint32_t baddr = sB + (uint32_t)(krow * 128 + ((gb ^ (krow & 7)) << 4));
        asm volatile("ldmatrix.sync.aligned.m8n8.x4.trans.shared.b16 {%0,%1,%2,%3}, [%4];\n"
                     : "=r"(b[nq][0]), "=r"(b[nq][1]), "=r"(b[nq][2]), "=r"(b[nq][3])
                     : "r"(baddr));
    }
#pragma unroll
    for (int mi = 0; mi < 4; ++mi)
#pragma unroll
        for (int nj = 0; nj < 4; ++nj) {
            float* c = acc[mi * 4 + nj];
            asm volatile("mma.sync.aligned.m16n8k16.row.col.f32.f16.f16.f32 "
                         "{%0,%1,%2,%3}, {%4,%5,%6,%7}, {%8,%9}, {%0,%1,%2,%3};\n"
                         : "+f"(c[0]), "+f"(c[1]), "+f"(c[2]), "+f"(c[3])
                         : "r"(a[mi][0]), "r"(a[mi][1]), "r"(a[mi][2]), "r"(a[mi][3]),
                           "r"(b[nj >> 1][(nj & 1) * 2]),
                           "r"(b[nj >> 1][(nj & 1) * 2 + 1]));
        }
}

// STG-stage pipelined GEMM over nch 128-k chunks (all streamed via TMA bulk)
__device__ __forceinline__ void gemm_tile(
    const __half* __restrict__ WpA, const Seg segs[3], int nch,
    float (&acc)[16][4], int tid, uint32_t base, unsigned& gbase)
{
    const int lane = tid & 31, wid = tid >> 5;
    const int g = wid & 7, nh = wid >> 3;
    const uint32_t smA = base + A_OFF, smB = base + B_OFF, bars = base + BAR_OFF;
    if (tid == 0) {
        asm volatile("fence.proxy.async.shared::cta;\n" ::: "memory");
#pragma unroll
        for (int j0 = 0; j0 < STG - 1; ++j0)
            if (j0 < nch) {
                unsigned gn = gbase + j0; int stn = (int)(gn % (unsigned)STG);
                issue_chunk(WpA, j0, segs, smA + stn * AB, smB + stn * BB,
                            bars + stn * 8);
            }
    }
    for (int j = 0; j < nch; ++j) {
        const unsigned gj = gbase + j;
        const int st = (int)(gj % (unsigned)STG);
        const unsigned use = gj / (unsigned)STG;
        mbar_wait(bars + st * 8, use & 1u);
        __syncthreads();              // all warps done with this stage's prior use
        const int jn = j + (STG - 1);
        if (tid == 0 && jn < nch) {
            unsigned gn = gbase + jn; int stn = (int)(gn % (unsigned)STG);
            issue_chunk(WpA, jn, segs, smA + stn * AB, smB + stn * BB,
                        bars + stn * 8);
        }
        compute_chunk(smA + st * AB, smB + st * BB, acc, lane, g, nh);
    }
    gbase += (unsigned)nch;
}

// store each warp's k-partial acc into its smem slab [64][33] f32
__device__ __forceinline__ void reduce_store(float (&acc)[16][4], int tid, char* smal)
{
    const int wid = tid >> 5, lane = tid & 31;
    float* slab = (float*)smal + wid * RSLAB;   // aliases stage smem (fenced)
    const int r = lane >> 2, c2 = (lane & 3) * 2;
#pragma unroll
    for (int mi = 0; mi < 4; ++mi)
#pragma unroll
        for (int nj = 0; nj < 4; ++nj) {
            float* p = slab + (mi * 16 + r) * 33 + nj * 8 + c2;
            p[0] = acc[mi * 4 + nj][0];
            p[1] = acc[mi * 4 + nj][1];
            p[33 * 8]     = acc[mi * 4 + nj][2];
            p[33 * 8 + 1] = acc[mi * 4 + nj][3];
        }
}

// LSTM pointwise: CTA owns 16 units; h written into the swizzled B image
__device__ __forceinline__ void epi_gates(
    float (&acc)[16][4], int tid, int tile, const float* __restrict__ bias,
    float* __restrict__ cbuf, __half* __restrict__ hpar, char* smal)
{
    const int m0 = tile * MR;
    __syncthreads();
    reduce_store(acc, tid, smal);
    __syncthreads();
    const float* red = (const float*)smal;
#pragma unroll
    for (int rep = 0; rep < 2; ++rep) {
        const int cell = tid + rep * NTHR;           // 1024 cells = 16u x 64b
        const int du = cell >> 6, b = cell & 63;
        const int nh = b >> 5, nl = b & 31;
        float gs[4];
#pragma unroll
        for (int j = 0; j < 4; ++j) {
            const int r = 4 * du + j;
            float s = 0.f;
#pragma unroll
            for (int g = 0; g < 8; ++g)
                s += red[(nh * 8 + g) * RSLAB + r * 33 + nl];
            gs[j] = s + bias[m0 + r];
        }
        const int uglob = tile * 16 + du;
        const int ci = uglob * Bb + b;
        float c = cbuf[ci];
        float cn = sigf(gs[1]) * c + sigf(gs[0]) * tanhf(gs[2]);
        cbuf[ci] = cn;
        hpar[(size_t)(uglob >> 7) * BCH + bswz(uglob & 127, b)] =
            __float2half(sigf(gs[3]) * tanhf(cn));
    }
    __syncthreads();
}

__device__ __forceinline__ void do_y(
    int tile, int t_y, int p, float* __restrict__ out, int tid,
    uint32_t base, unsigned& gbase, char* smal)
{
    const int m0 = (tile - NGT) * MR;
    float acc[16][4] = {};
    Seg segs[3] = { { g_xp + (size_t)t_y * (XCH * BCH), XCH },
                    { g_h2p + (size_t)p * HPH, HCH },
                    { nullptr, 0 } };
    gemm_tile(g_Wlp + (size_t)(tile - NGT) * (W1CH * ACH), segs, XCH + HCH,
              acc, tid, base, gbase);
    __syncthreads();
    reduce_store(acc, tid, smal);
    __syncthreads();
    const float* red = (const float*)smal;
#pragma unroll
    for (int rep = 0; rep < 2; ++rep) {
        const int cell = tid + rep * NTHR;           // 1024 cells = 16 quads x 64b
        const int du = cell >> 6, b = cell & 63;
        const int nh = b >> 5, nl = b & 31;
        float4 v;
        float* vv = &v.x;
#pragma unroll
        for (int j = 0; j < 4; ++j) {
            const int r = 4 * du + j;
            float s = 0.f;
#pragma unroll
            for (int g = 0; g < 8; ++g)
                s += red[(nh * 8 + g) * RSLAB + r * 33 + nl];
            vv[j] = s + g_bl[m0 + r];
        }
        *(float4*)(out + (size_t)b * (Tt * Oo) + (size_t)t_y * Oo + m0 + 4 * du) = v;
    }
    __syncthreads();
}

// ---------------- persistent LSTM kernel ----------------
__global__ void __launch_bounds__(NTHR, 1) lstm_main(float* __restrict__ out) {
    extern __shared__ __align__(16) char smem_raw[];
    const uint32_t sb = (uint32_t)__cvta_generic_to_shared(smem_raw);
    const uint32_t base = (sb + 1023) & ~1023u;
    char* smal = smem_raw + (base - sb);
    const uint32_t bars = base + BAR_OFF;
    const int tile = blockIdx.x;
    const int tid = threadIdx.x;

    if (tid == 0) {
#pragma unroll
        for (int s = 0; s < STG; ++s)
            asm volatile("mbarrier.init.shared.b64 [%0], 1;\n"
                         :: "r"(bars + s * 8) : "memory");
        asm volatile("fence.proxy.async.shared::cta;\n" ::: "memory");
    }
    __syncthreads();

    unsigned gch = 0, ph = 0;
    for (int t = 0; t <= Tt; ++t) {
        const int p = t & 1;
        // ---- Phase A: gates1(t) on tiles 0..63 ; y(t-1) on tiles 64..67
        if (t < Tt) {
            if (tile < NGT) {
                float acc[16][4] = {};
                Seg segs[3] = { { g_xp + (size_t)t * (XCH * BCH), XCH },
                                { g_h1p + (size_t)(1 - p) * HPH, HCH },
                                { nullptr, 0 } };
                gemm_tile(g_W1p + (size_t)tile * (W1CH * ACH), segs, XCH + HCH,
                          acc, tid, base, gch);
                epi_gates(acc, tid, tile, g_b1, g_c1, g_h1p + (size_t)p * HPH, smal);
            } else if (t > 0) {
                do_y(tile, t - 1, p, out, tid, base, gch, smal);
            }
        } else {
            if (tile >= NGT) do_y(tile, t - 1, p, out, tid, base, gch, smal);
            break;
        }
        ph++; gbar(ph * NBLK);
        // ---- Phase B: gates2(t) on tiles 0..63
        if (tile < NGT) {
            float acc[16][4] = {};
            Seg segs[3] = { { g_xp + (size_t)t * (XCH * BCH), XCH },
                            { g_h1p + (size_t)p * HPH, HCH },
                            { g_h2p + (size_t)p * HPH, HCH } };
            gemm_tile(g_W2p + (size_t)tile * (W2CH * ACH), segs, XCH + 2 * HCH,
                      acc, tid, base, gch);
            epi_gates(acc, tid, tile, g_b2, g_c2, g_h2p + (size_t)(1 - p) * HPH, smal);
        }
        ph++; gbar(ph * NBLK);
    }
}

// ---------------- launch ----------------
extern "C" void kernel_launch(void* const* d_in, const int* in_sizes, int n_in,
                              void* d_out, int out_size) {
    const float* x    = (const float*)d_in[0];
    const float* Wih1 = (const float*)d_in[1];
    const float* Whh1 = (const float*)d_in[2];
    const float* bih1 = (const float*)d_in[3];
    const float* bhh1 = (const float*)d_in[4];
    const float* Wih2 = (const float*)d_in[5];
    const float* Whh2 = (const float*)d_in[6];
    const float* bih2 = (const float*)d_in[7];
    const float* bhh2 = (const float*)d_in[8];
    const float* Wl   = (const float*)d_in[9];
    const float* bl   = (const float*)d_in[10];
    float* out = (float*)d_out;

    cudaFuncSetAttribute(lstm_main, cudaFuncAttributeMaxDynamicSharedMemorySize,
                         SMEM_TOTAL);

    const size_t nprep = (size_t)NGT * W2CH * ACH;   // largest packed array
    prep_all<<<(unsigned)((nprep + 255) / 256), 256>>>(
        x, Wih1, Whh1, bih1, bhh1, Wih2, Whh2, bih2, bhh2, Wl, bl);
    lstm_main<<<NBLK, NTHR, SMEM_TOTAL>>>(out);
}

// round 15
// speedup vs baseline: 1.6080x; 1.6080x over previous
#include <cuda_runtime.h>
#include <cuda_fp16.h>
#include <cstdint>

#define Bb   64
#define Tt   256
#define Ii   256
#define Hh   1024
#define Gg   4096
#define Oo   256
#define NBLK 136
#define NTHR 512
#define CH   256            // k per chunk
#define ACH  8192           // halves per A chunk (32 rows x 256, swizzled)
#define BCH  16384          // halves per B chunk (256 rows x 64, swizzled)
#define AB   (ACH * 2)      // 16384 B
#define BB   (BCH * 2)      // 32768 B
#define STG  4
#define W1CH 5              // (I+H)/256
#define W2CH 9              // (I+H+H)/256
#define XCH  1              // I/256
#define HCH  4              // H/256
#define HPH  (HCH * BCH)    // halves per h parity buffer
#define RSLAB 1056          // 32*33 floats per warp partial slab

// smem layout (byte offsets from 1024-aligned base)
#define A_OFF  0
#define B_OFF  (STG * AB)                 // 65536
#define BAR_OFF (B_OFF + STG * BB)        // 196608
#define SMEM_USED (BAR_OFF + 64)
#define SMEM_TOTAL (SMEM_USED + 1024)

// ---------------- device-global scratch (packed swizzled smem images) --------
__device__ __align__(16) __half g_W1p[(size_t)128 * W1CH * ACH];
__device__ __align__(16) __half g_W2p[(size_t)128 * W2CH * ACH];
__device__ __align__(16) __half g_Wlp[(size_t)8 * W1CH * ACH];
__device__ __align__(16) __half g_xp [(size_t)Tt * XCH * BCH];
__device__ __align__(16) __half g_h1p[2 * HPH];
__device__ __align__(16) __half g_h2p[2 * HPH];
__device__ float g_c1[Hh * Bb];
__device__ float g_c2[Hh * Bb];
__device__ float g_b1[Gg];
__device__ float g_b2[Gg];
__device__ float g_bl[Oo];
__device__ unsigned g_bar;

// swizzled offsets (halves): 16B groups XORed by row&7 -> conflict-free ldmatrix
__device__ __forceinline__ uint32_t aswz(int row, int k) {   // A: 256-half rows
    return (uint32_t)(row * 256 + (((k >> 3) ^ (row & 7)) << 3) + (k & 7));
}
__device__ __forceinline__ uint32_t bswz(int krow, int b) {  // B: 64-half rows
    return (uint32_t)(krow * 64 + (((b >> 3) ^ (krow & 7)) << 3) + (b & 7));
}

// ---------------- merged prep kernel ----------------
__global__ void prep_all(
    const float* __restrict__ x,
    const float* __restrict__ Wih1, const float* __restrict__ Whh1,
    const float* __restrict__ bi1,  const float* __restrict__ bh1,
    const float* __restrict__ Wih2, const float* __restrict__ Whh2,
    const float* __restrict__ bi2,  const float* __restrict__ bh2,
    const float* __restrict__ Wl,   const float* __restrict__ bl)
{
    const size_t idx = (size_t)blockIdx.x * blockDim.x + threadIdx.x;

    // W2p: logical [tile 128][chunk 9][row 32][k 256] -> swizzled image
    if (idx < (size_t)128 * W2CH * ACH) {
        int tile = (int)(idx / (W2CH * ACH));
        int r1 = (int)(idx - (size_t)tile * (W2CH * ACH));
        int chunk = r1 / ACH, r2 = r1 - chunk * ACH;
        int row = r2 >> 8, k = r2 & 255;
        int gr = tile * 32 + row;
        int u = gr >> 2, gt = gr & 3, orow = gt * Hh + u;
        int kk = chunk * CH + k;
        float v = (kk < Ii + Hh) ? Wih2[(size_t)orow * (Ii + Hh) + kk]
                                 : Whh2[(size_t)orow * Hh + (kk - Ii - Hh)];
        g_W2p[((size_t)tile * W2CH + chunk) * ACH + aswz(row, k)] = __float2half(v);
    }
    // W1p: [tile 128][chunk 5][row 32][k 256]
    if (idx < (size_t)128 * W1CH * ACH) {
        int tile = (int)(idx / (W1CH * ACH));
        int r1 = (int)(idx - (size_t)tile * (W1CH * ACH));
        int chunk = r1 / ACH, r2 = r1 - chunk * ACH;
        int row = r2 >> 8, k = r2 & 255;
        int gr = tile * 32 + row;
        int u = gr >> 2, gt = gr & 3, orow = gt * Hh + u;
        int kk = chunk * CH + k;
        float v = (kk < Ii) ? Wih1[(size_t)orow * Ii + kk]
                            : Whh1[(size_t)orow * Hh + (kk - Ii)];
        g_W1p[((size_t)tile * W1CH + chunk) * ACH + aswz(row, k)] = __float2half(v);
    }
    // Wlp: [tile 8][chunk 5][row 32][k 256] (no gate permute)
    if (idx < (size_t)8 * W1CH * ACH) {
        int tile = (int)(idx / (W1CH * ACH));
        int r1 = (int)(idx - (size_t)tile * (W1CH * ACH));
        int chunk = r1 / ACH, r2 = r1 - chunk * ACH;
        int row = r2 >> 8, k = r2 & 255;
        int m = tile * 32 + row;
        int kk = chunk * CH + k;
        float v = Wl[(size_t)m * (Ii + Hh) + kk];
        g_Wlp[((size_t)tile * W1CH + chunk) * ACH + aswz(row, k)] = __float2half(v);
    }
    // xp: logical [t][krow 256][b 64]
    if (idx < (size_t)Tt * XCH * BCH) {
        int t = (int)(idx / (XCH * BCH));
        int r2 = (int)(idx - (size_t)t * (XCH * BCH));
        int krow = r2 >> 6, b = r2 & 63;
        float v = x[((size_t)b * Tt + t) * Ii + krow];
        g_xp[(size_t)t * BCH + bswz(krow, b)] = __float2half(v);
    }
    if (idx < 2 * HPH) { g_h1p[idx] = __float2half(0.f); g_h2p[idx] = __float2half(0.f); }
    if (idx < Hh * Bb) { g_c1[idx] = 0.f; g_c2[idx] = 0.f; }
    if (idx < Gg) {
        int u = (int)idx >> 2, gt = (int)idx & 3;
        g_b1[idx] = bi1[gt * Hh + u] + bh1[gt * Hh + u];
        g_b2[idx] = bi2[gt * Hh + u] + bh2[gt * Hh + u];
    }
    if (idx < Oo) g_bl[idx] = bl[idx];
    if (idx == 0) g_bar = 0u;
}

// ---------------- helpers ----------------
struct Seg { const __half* z; int chunks; };

__device__ __forceinline__ float sigf(float x) { return 1.f / (1.f + __expf(-x)); }

__device__ __forceinline__ void gbar(unsigned target) {
    __syncthreads();
    if (threadIdx.x == 0) {
        asm volatile("red.release.gpu.global.add.u32 [%0], %1;\n"
                     :: "l"(&g_bar), "r"(1u) : "memory");
        unsigned v;
        do {
            asm volatile("ld.acquire.gpu.global.u32 %0, [%1];\n"
                         : "=r"(v) : "l"(&g_bar) : "memory");
        } while (v < target);
    }
    __syncthreads();
}

__device__ __forceinline__ void mbar_wait(uint32_t bar, unsigned parity) {
    asm volatile(
        "{\n\t.reg .pred P;\n"
        "WAIT_%=:\n\t"
        "mbarrier.try_wait.parity.shared.b64 P, [%0], %1;\n\t"
        "@P bra.uni DONE_%=;\n\t"
        "bra.uni WAIT_%=;\n"
        "DONE_%=:\n\t}"
        :: "r"(bar), "r"(parity) : "memory");
}

__device__ __forceinline__ void bulk_to(uint32_t dst, const void* src, unsigned bytes,
                                        uint32_t bar) {
    asm volatile("cp.async.bulk.shared::cta.global.mbarrier::complete_tx::bytes "
                 "[%0], [%1], %2, [%3];\n"
                 :: "r"(dst), "l"(src), "r"(bytes), "r"(bar) : "memory");
}

// issue one chunk's A (weight) + B (z) bulk copies; tid 0 only
__device__ __forceinline__ void issue_chunk(
    const __half* __restrict__ WpA, int j, const Seg segs[3],
    uint32_t sA, uint32_t sB, uint32_t bar)
{
    asm volatile("mbarrier.arrive.expect_tx.shared.b64 _, [%0], %1;\n"
                 :: "r"(bar), "r"((unsigned)(AB + BB)) : "memory");
    bulk_to(sA, WpA + (size_t)j * ACH, AB, bar);
    int jj = j, s = 0;
    if (jj >= segs[0].chunks) { jj -= segs[0].chunks; s = 1; }
    if (s == 1 && jj >= segs[1].chunks) { jj -= segs[1].chunks; s = 2; }
    bulk_to(sB, segs[s].z + (size_t)jj * BCH, BB, bar);
}

// compute one 256-k chunk; warp owns 32m x 32n x 32k (g = k-group, nh = n-half)
__device__ __forceinline__ void compute_chunk(
    uint32_t sA, uint32_t sB, float (&acc)[8][4], int lane, int g, int nh)
{
    const int r16 = lane & 15, cs = lane >> 4;
#pragma unroll
    for (int kk2 = 0; kk2 < 2; ++kk2) {
        const int k16 = g * 2 + kk2;                 // k16 block 0..15
        unsigned a[2][4], b[2][4];
#pragma unroll
        for (int mi = 0; mi < 2; ++mi) {
            const int row = mi * 16 + r16;
            const int ga = k16 * 2 + cs;             // 16B group within 512B row
            uint32_t aaddr = sA + (uint32_t)(row * 512 + ((ga ^ (row & 7)) << 4));
            asm volatile("ldmatrix.sync.aligned.m8n8.x4.shared.b16 {%0,%1,%2,%3}, [%4];\n"
                         : "=r"(a[mi][0]), "=r"(a[mi][1]), "=r"(a[mi][2]), "=r"(a[mi][3])
                         : "r"(aaddr));
        }
#pragma unroll
        for (int nq = 0; nq < 2; ++nq) {
            const int krow = k16 * 16 + r16;
            const int gb = nh * 4 + nq * 2 + cs;     // 16B group within 128B row
            uint32_t baddr = sB + (uint32_t)(krow * 128 + ((gb ^ (krow & 7)) << 4));
            asm volatile("ldmatrix.sync.aligned.m8n8.x4.trans.shared.b16 {%0,%1,%2,%3}, [%4];\n"
                         : "=r"(b[nq][0]), "=r"(b[nq][1]), "=r"(b[nq][2]), "=r"(b[nq][3])
                         : "r"(baddr));
        }
#pragma unroll
        for (int mi = 0; mi < 2; ++mi)
#pragma unroll
            for (int nj = 0; nj < 4; ++nj) {
                float* c = acc[mi * 4 + nj];
                asm volatile("mma.sync.aligned.m16n8k16.row.col.f32.f16.f16.f32 "
                             "{%0,%1,%2,%3}, {%4,%5,%6,%7}, {%8,%9}, {%0,%1,%2,%3};\n"
                             : "+f"(c[0]), "+f"(c[1]), "+f"(c[2]), "+f"(c[3])
                             : "r"(a[mi][0]), "r"(a[mi][1]), "r"(a[mi][2]), "r"(a[mi][3]),
                               "r"(b[nj >> 1][(nj & 1) * 2]),
                               "r"(b[nj >> 1][(nj & 1) * 2 + 1]));
            }
    }
}

// STG-stage pipelined GEMM over nch 256-k chunks (all streamed via TMA bulk)
__device__ __forceinline__ void gemm_tile(
    const __half* __restrict__ WpA, const Seg segs[3], int nch,
    float (&acc)[8][4], int tid, uint32_t base, unsigned& gbase)
{
    const int lane = tid & 31, wid = tid >> 5;
    const int g = wid & 7, nh = wid >> 3;
    const uint32_t smA = base + A_OFF, smB = base + B_OFF, bars = base + BAR_OFF;
    if (tid == 0) {
        asm volatile("fence.proxy.async.shared::cta;\n" ::: "memory");
#pragma unroll
        for (int j0 = 0; j0 < STG - 1; ++j0)
            if (j0 < nch) {
                unsigned gn = gbase + j0; int stn = (int)(gn % (unsigned)STG);
                issue_chunk(WpA, j0, segs, smA + stn * AB, smB + stn * BB,
                            bars + stn * 8);
            }
    }
    for (int j = 0; j < nch; ++j) {
        const unsigned gj = gbase + j;
        const int st = (int)(gj % (unsigned)STG);
        const unsigned use = gj / (unsigned)STG;
        mbar_wait(bars + st * 8, use & 1u);
        __syncthreads();              // all warps done with this stage's prior use
        const int jn = j + (STG - 1);
        if (tid == 0 && jn < nch) {
            unsigned gn = gbase + jn; int stn = (int)(gn % (unsigned)STG);
            issue_chunk(WpA, jn, segs, smA + stn * AB, smB + stn * BB,
                        bars + stn * 8);
        }
        compute_chunk(smA + st * AB, smB + st * BB, acc, lane, g, nh);
    }
    gbase += (unsigned)nch;
}

// store each warp's k-partial acc into its smem slab [32][33] f32
__device__ __forceinline__ void reduce_store(float (&acc)[8][4], int tid, char* smal)
{
    const int wid = tid >> 5, lane = tid & 31;
    float* slab = (float*)smal + wid * RSLAB;   // aliases stage smem (fenced)
    const int r = lane >> 2, c2 = (lane & 3) * 2;
#pragma unroll
    for (int mi = 0; mi < 2; ++mi)
#pragma unroll
        for (int nj = 0; nj < 4; ++nj) {
            float* p = slab + (mi * 16 + r) * 33 + nj * 8 + c2;
            p[0] = acc[mi * 4 + nj][0];
            p[1] = acc[mi * 4 + nj][1];
            p[33 * 8]     = acc[mi * 4 + nj][2];
            p[33 * 8 + 1] = acc[mi * 4 + nj][3];
        }
}

// LSTM pointwise: CTA owns 8 units; h written into the swizzled B image
__device__ __forceinline__ void epi_gates(
    float (&acc)[8][4], int tid, int tile, const float* __restrict__ bias,
    float* __restrict__ cbuf, __half* __restrict__ hpar, char* smal)
{
    const int m0 = tile * 32;
    __syncthreads();
    reduce_store(acc, tid, smal);
    __syncthreads();
    const float* red = (const float*)smal;
    const int du = tid >> 6, b = tid & 63;
    const int nh = b >> 5, nl = b & 31;
    float gs[4];
#pragma unroll
    for (int j = 0; j < 4; ++j) {
        float s = 0.f;
#pragma unroll
        for (int g = 0; g < 8; ++g)
            s += red[(nh * 8 + g) * RSLAB + (4 * du + j) * 33 + nl];
        gs[j] = s + bias[m0 + 4 * du + j];
    }
    const int uglob = tile * 8 + du;
    const int ci = uglob * Bb + b;
    float c = cbuf[ci];
    float cn = sigf(gs[1]) * c + sigf(gs[0]) * tanhf(gs[2]);
    cbuf[ci] = cn;
    hpar[(size_t)(uglob >> 8) * BCH + bswz(uglob & 255, b)] =
        __float2half(sigf(gs[3]) * tanhf(cn));
    __syncthreads();
}

__device__ __forceinline__ void do_y(
    int tile, int t_y, int p, float* __restrict__ out, int tid,
    uint32_t base, unsigned& gbase, char* smal)
{
    const int m0 = (tile - 128) * 32;
    float acc[8][4] = {};
    Seg segs[3] = { { g_xp + (size_t)t_y * (XCH * BCH), XCH },
                    { g_h2p + (size_t)p * HPH, HCH },
                    { nullptr, 0 } };
    gemm_tile(g_Wlp + (size_t)(tile - 128) * (W1CH * ACH), segs, XCH + HCH,
              acc, tid, base, gbase);
    __syncthreads();
    reduce_store(acc, tid, smal);
    __syncthreads();
    const float* red = (const float*)smal;
    const int du = tid >> 6, b = tid & 63;
    const int nh = b >> 5, nl = b & 31;
    float4 v;
    float* vv = &v.x;
#pragma unroll
    for (int j = 0; j < 4; ++j) {
        float s = 0.f;
#pragma unroll
        for (int g = 0; g < 8; ++g)
            s += red[(nh * 8 + g) * RSLAB + (4 * du + j) * 33 + nl];
        vv[j] = s + g_bl[m0 + 4 * du + j];
    }
    *(float4*)(out + (size_t)b * (Tt * Oo) + (size_t)t_y * Oo + m0 + 4 * du) = v;
    __syncthreads();
}

// ---------------- persistent LSTM kernel ----------------
__global__ void __launch_bounds__(NTHR, 1) lstm_main(float* __restrict__ out) {
    extern __shared__ __align__(16) char smem_raw[];
    const uint32_t sb = (uint32_t)__cvta_generic_to_shared(smem_raw);
    const uint32_t base = (sb + 1023) & ~1023u;
    char* smal = smem_raw + (base - sb);
    const uint32_t bars = base + BAR_OFF;
    const int tile = blockIdx.x;
    const int tid = threadIdx.x;

    if (tid == 0) {
#pragma unroll
        for (int s = 0; s < STG; ++s)
            asm volatile("mbarrier.init.shared.b64 [%0], 1;\n"
                         :: "r"(bars + s * 8) : "memory");
        asm volatile("fence.proxy.async.shared::cta;\n" ::: "memory");
    }
    __syncthreads();

    unsigned gch = 0, ph = 0;
    for (int t = 0; t <= Tt; ++t) {
        const int p = t & 1;
        // ---- Phase A: gates1(t) on tiles 0..127 ; y(t-1) on tiles 128..135
        if (t < Tt) {
            if (tile < 128) {
                float acc[8][4] = {};
                Seg segs[3] = { { g_xp + (size_t)t * (XCH * BCH), XCH },
                                { g_h1p + (size_t)(1 - p) * HPH, HCH },
                                { nullptr, 0 } };
                gemm_tile(g_W1p + (size_t)tile * (W1CH * ACH), segs, XCH + HCH,
                          acc, tid, base, gch);
                epi_gates(acc, tid, tile, g_b1, g_c1, g_h1p + (size_t)p * HPH, smal);
            } else if (t > 0) {
                do_y(tile, t - 1, p, out, tid, base, gch, smal);
            }
        } else {
            if (tile >= 128) do_y(tile, t - 1, p, out, tid, base, gch, smal);
            break;
        }
        ph++; gbar(ph * NBLK);
        // ---- Phase B: gates2(t) on tiles 0..127
        if (tile < 128) {
            float acc[8][4] = {};
            Seg segs[3] = { { g_xp + (size_t)t * (XCH * BCH), XCH },
                            { g_h1p + (size_t)p * HPH, HCH },
                            { g_h2p + (size_t)p * HPH, HCH } };
            gemm_tile(g_W2p + (size_t)tile * (W2CH * ACH), segs, XCH + 2 * HCH,
                      acc, tid, base, gch);
            epi_gates(acc, tid, tile, g_b2, g_c2, g_h2p + (size_t)(1 - p) * HPH, smal);
        }
        ph++; gbar(ph * NBLK);
    }
}

// ---------------- launch ----------------
extern "C" void kernel_launch(void* const* d_in, const int* in_sizes, int n_in,
                              void* d_out, int out_size) {
    const float* x    = (const float*)d_in[0];
    const float* Wih1 = (const float*)d_in[1];
    const float* Whh1 = (const float*)d_in[2];
    const float* bih1 = (const float*)d_in[3];
    const float* bhh1 = (const float*)d_in[4];
    const float* Wih2 = (const float*)d_in[5];
    const float* Whh2 = (const float*)d_in[6];
    const float* bih2 = (const float*)d_in[7];
    const float* bhh2 = (const float*)d_in[8];
    const float* Wl   = (const float*)d_in[9];
    const float* bl   = (const float*)d_in[10];
    float* out = (float*)d_out;

    cudaFuncSetAttribute(lstm_main, cudaFuncAttributeMaxDynamicSharedMemorySize,
                         SMEM_TOTAL);

    const size_t nprep = (size_t)128 * W2CH * ACH;   // largest packed array
    prep_all<<<(unsigned)((nprep + 255) / 256), 256>>>(
        x, Wih1, Whh1, bih1, bhh1, Wih2, Whh2, bih2, bhh2, Wl, bl);
    lstm_main<<<NBLK, NTHR, SMEM_TOTAL>>>(out);
}